// round 1
// baseline (speedup 1.0000x reference)
#include <cuda_runtime.h>
#include <cuda_bf16.h>

// Problem constants (fixed shapes per setup_inputs)
#define Bn 8
#define Rn 4096
#define Gn 512
#define OUTG (Gn * 35)
#define OUTW (Gn * 35 + Rn * 2)   // 26112 floats per batch row

__constant__ int   c_group[10] = {0,1,1,2,2,3,4,4,5,5};
__constant__ float c_high[10]  = {2.0f,2.5f,2.5f,3.5f,2.5f,0.5f,1.0f,1.0f,0.5f,0.5f};
__constant__ float c_med[10]   = {4.0f,4.0f,4.0f,4.0f,4.0f,2.5f,2.5f,2.5f,2.0f,2.0f};

// Scratch (no dynamic allocation allowed)
__device__ float4 g_roi[Bn * Rn];      // x, y, score, meta(grp | valid<<8) as float bits
__device__ float4 g_gtA[Bn * Gn];      // gx, gy, T_high(d^2), T_med(d^2)
__device__ int    g_gtmeta[Bn * Gn];   // grp+256 if valid else -1000
__device__ float2 g_gtxy[Bn * Gn];     // gt xy for FP pass; invalid -> 1e20 (d^2 = inf)

// Largest float T with sqrt_rn(T) <= t, so (d2 <= T) <=> (sqrt_rn(d2) <= t)
// bit-exactly. t and t*t are exactly representable for all table values.
__device__ __forceinline__ float adjust_thresh(float t) {
    float T = __fmul_rn(t, t);
    while (__fsqrt_rn(T) > t)
        T = __int_as_float(__float_as_int(T) - 1);
    for (;;) {
        float y = __int_as_float(__float_as_int(T) + 1);
        if (__fsqrt_rn(y) <= t) T = y; else break;
    }
    return T;
}

__global__ void ptl_pack_kernel(const float* __restrict__ rois,
                                const float* __restrict__ scores,
                                const int*   __restrict__ labels,
                                const float* __restrict__ gt) {
    int i = blockIdx.x * blockDim.x + threadIdx.x;
    if (i < Bn * Rn) {
        const float* rp = rois + (size_t)i * 9;
        float s = 0.f;
        #pragma unroll
        for (int k = 0; k < 9; k++) s += rp[k];
        bool valid = (s != 0.f);
        int lab = labels[i];
        lab = min(max(lab, 0), 9);
        int grp = c_group[lab];
        float4 p;
        p.x = rp[0];
        p.y = rp[1];
        p.z = scores[i];
        p.w = __int_as_float(grp + (valid ? 256 : 0));
        g_roi[i] = p;
    }
    int j = i - Bn * Rn;
    if (j >= 0 && j < Bn * Gn) {
        const float* gp = gt + (size_t)j * 10;
        float s = 0.f;
        #pragma unroll
        for (int k = 0; k < 10; k++) s += gp[k];
        bool valid = (s != 0.f);
        int cls = (int)gp[9];           // trunc-toward-zero, saturating cvt
        cls = min(max(cls, 0), 9);
        int grp = c_group[cls];
        float4 a;
        a.x = gp[0];
        a.y = gp[1];
        a.z = adjust_thresh(c_high[cls]);
        a.w = adjust_thresh(c_med[cls]);
        g_gtA[j] = a;
        g_gtmeta[j] = valid ? (grp + 256) : -1000;
        float2 xy;
        if (valid) { xy.x = gp[0]; xy.y = gp[1]; }
        else       { xy.x = 1e20f; xy.y = 0.f;  }
        g_gtxy[j] = xy;
    }
}

#define GT_BLOCKS ((Bn * Gn) / 8)      // 8 warps/block, 1 warp = 1 GT -> 512 blocks
#define FP_BLOCKS ((Bn * Rn) / 256)    // 256 threads/block, 1 thread = 1 ROI -> 128

__global__ void __launch_bounds__(256)
ptl_main_kernel(const float* __restrict__ rois,
                const float* __restrict__ gt,
                float* __restrict__ out) {
    if (blockIdx.x < GT_BLOCKS) {
        // ---- per-GT scan over all R ROIs: one warp per GT ----
        int warp = (blockIdx.x * blockDim.x + threadIdx.x) >> 5;  // 0..4095
        int lane = threadIdx.x & 31;
        int b = warp >> 9;
        int g = warp & (Gn - 1);

        int   meta = g_gtmeta[warp];
        float4 ga  = g_gtA[warp];
        float gx = ga.x, gy = ga.y, Th = ga.z, Tm = ga.w;

        float bestH = -1.f; int idxH = -1;
        float bestM = -1.f; int idxM = -1;

        if (meta > 0) {
            const float4* rp = g_roi + b * Rn;
            #pragma unroll 4
            for (int r = lane; r < Rn; r += 32) {
                float4 p = __ldg(&rp[r]);
                float dx = __fadd_rn(p.x, -gx);
                float dy = __fadd_rn(p.y, -gy);
                float d2 = __fadd_rn(__fmul_rn(dx, dx), __fmul_rn(dy, dy));
                if (__float_as_int(p.w) == meta) {
                    if (d2 <= Th) {
                        if (p.z > bestH) { bestH = p.z; idxH = r; }
                    } else if (d2 <= Tm) {
                        if (p.z > bestM) { bestM = p.z; idxM = r; }
                    }
                }
            }
        }

        // warp reduce: max score, ties -> lowest index (matches jnp.argmax)
        #pragma unroll
        for (int off = 16; off; off >>= 1) {
            float sH = __shfl_down_sync(0xffffffffu, bestH, off);
            int   iH = __shfl_down_sync(0xffffffffu, idxH,  off);
            if (iH >= 0 && (sH > bestH || (sH == bestH && (idxH < 0 || iH < idxH)))) {
                bestH = sH; idxH = iH;
            }
            float sM = __shfl_down_sync(0xffffffffu, bestM, off);
            int   iM = __shfl_down_sync(0xffffffffu, idxM,  off);
            if (iM >= 0 && (sM > bestM || (sM == bestM && (idxM < 0 || iM < idxM)))) {
                bestM = sM; idxM = iM;
            }
        }

        if (lane == 0) {
            float* o = out + (size_t)b * OUTW + g * 35;
            bool hv = (idxH >= 0);
            bool has_med = (idxM >= 0);
            bool mv = (!hv) && has_med;
            bool matched = hv || mv;
            bool gvalid = (meta > 0);

            // [0:9] high_roi*hv, [9] refined*hv, [10] hv
            if (hv) {
                const float* hr = rois + ((size_t)b * Rn + idxH) * 9;
                #pragma unroll
                for (int k = 0; k < 9; k++) o[k] = hr[k];
                o[9]  = fminf(__fmul_rn(__fadd_rn(1.2f, bestH), 0.5f), 1.0f);
                o[10] = 1.0f;
            } else {
                #pragma unroll
                for (int k = 0; k < 11; k++) o[k] = 0.0f;
            }
            // [11:20] med_roi*mv, [20] med_score*mv, [21] mv
            if (mv) {
                const float* mr = rois + ((size_t)b * Rn + idxM) * 9;
                #pragma unroll
                for (int k = 0; k < 9; k++) o[11 + k] = mr[k];
                o[20] = bestM;
                o[21] = 1.0f;
            } else {
                #pragma unroll
                for (int k = 11; k < 22; k++) o[k] = 0.0f;
            }
            // [22:32] gt*matched
            const float* gtr = gt + ((size_t)b * Gn + g) * 10;
            if (matched) {
                #pragma unroll
                for (int k = 0; k < 10; k++) o[22 + k] = gtr[k];
            } else {
                #pragma unroll
                for (int k = 0; k < 10; k++) o[22 + k] = 0.0f;
            }
            // [32:35] near, mid, far  (unmatched range buckets)
            bool unmatched = gvalid && !hv && !has_med;
            float nearf = 0.f, midf = 0.f, farf = 0.f;
            if (unmatched) {
                float rng = __fsqrt_rn(__fadd_rn(__fmul_rn(gx, gx), __fmul_rn(gy, gy)));
                if (rng < 30.0f)      nearf = 1.f;
                else if (rng > 50.0f) farf  = 1.f;
                else                  midf  = 1.f;
            }
            o[32] = nearf; o[33] = midf; o[34] = farf;
        }
    } else {
        // ---- per-ROI false-positive pass: one thread per ROI ----
        int bb = blockIdx.x - GT_BLOCKS;          // 0..127
        int b  = bb >> 4;                          // 16 blocks per batch
        int r  = ((bb & 15) << 8) + threadIdx.x;   // 0..4095

        __shared__ float2 sgt[Gn];
        for (int j = threadIdx.x; j < Gn; j += 256)
            sgt[j] = g_gtxy[b * Gn + j];
        __syncthreads();

        float4 p = g_roi[b * Rn + r];
        float x = p.x, y = p.y;
        float mind2 = __int_as_float(0x7f800000); // +inf
        #pragma unroll 8
        for (int j = 0; j < Gn; j++) {
            float dx = __fadd_rn(x, -sgt[j].x);
            float dy = __fadd_rn(y, -sgt[j].y);
            float d2 = __fadd_rn(__fmul_rn(dx, dx), __fmul_rn(dy, dy));
            mind2 = fminf(mind2, d2);
        }
        bool valid = (__float_as_int(p.w) & 256) != 0;
        bool fp = valid && (__fsqrt_rn(mind2) > 4.0f);
        float2 o2;
        o2.x = fp ? p.z : 0.f;
        o2.y = fp ? 1.f : 0.f;
        *(float2*)(out + (size_t)b * OUTW + OUTG + (size_t)r * 2) = o2;
    }
}

extern "C" void kernel_launch(void* const* d_in, const int* in_sizes, int n_in,
                              void* d_out, int out_size) {
    const float* rois   = (const float*)d_in[0];
    const float* scores = (const float*)d_in[1];
    const float* gt     = (const float*)d_in[2];
    const int*   labels = (const int*)d_in[3];
    float* out = (float*)d_out;

    int packN = Bn * Rn + Bn * Gn;
    ptl_pack_kernel<<<(packN + 255) / 256, 256>>>(rois, scores, labels, gt);
    ptl_main_kernel<<<GT_BLOCKS + FP_BLOCKS, 256>>>(rois, gt, out);
}

// round 2
// speedup vs baseline: 1.4272x; 1.4272x over previous
#include <cuda_runtime.h>
#include <cuda_bf16.h>

// Fixed shapes per setup_inputs
#define Bn 8
#define Rn 4096
#define Gn 512
#define NG 6
#define OUTG (Gn * 35)
#define OUTW (Gn * 35 + Rn * 2)   // 26112 floats per batch row

__constant__ int   c_group[10] = {0,1,1,2,2,3,4,4,5,5};
__constant__ float c_high[10]  = {2.0f,2.5f,2.5f,3.5f,2.5f,0.5f,1.0f,1.0f,0.5f,0.5f};
__constant__ float c_med[10]   = {4.0f,4.0f,4.0f,4.0f,4.0f,2.5f,2.5f,2.5f,2.0f,2.0f};

// Static scratch (no dynamic allocation allowed)
__device__ float4 g_roi[Bn * Rn];          // x, y, score, meta(grp | valid<<8) bits
__device__ float4 g_bucket[Bn * NG * Rn];  // per (batch,group): x, y, score, orig idx bits
__device__ int    g_bcnt[Bn * NG];         // bucket sizes
__device__ float4 g_gtA[Bn * Gn];          // gx, gy, T_high(d^2), T_med(d^2)
__device__ int    g_gtmeta[Bn * Gn];       // grp (0..5) if valid else -1
__device__ float2 g_gtxy[Bn * Gn];         // gt xy for FP pass; invalid -> 1e20

// Largest float T with sqrt_rn(T) <= t, so (d2 <= T) <=> (sqrt_rn(d2) <= t) bit-exactly.
__device__ __forceinline__ float adjust_thresh(float t) {
    float T = __fmul_rn(t, t);
    while (__fsqrt_rn(T) > t)
        T = __int_as_float(__float_as_int(T) - 1);
    for (;;) {
        float y = __int_as_float(__float_as_int(T) + 1);
        if (__fsqrt_rn(y) <= t) T = y; else break;
    }
    return T;
}

// One block per batch: pack ROIs + GTs, and scatter valid ROIs into per-group buckets.
__global__ void __launch_bounds__(1024)
ptl_pack_kernel(const float* __restrict__ rois,
                const float* __restrict__ scores,
                const int*   __restrict__ labels,
                const float* __restrict__ gt) {
    int b   = blockIdx.x;
    int tid = threadIdx.x;
    int lane = tid & 31;

    __shared__ int sh_cur[NG];
    if (tid < NG) sh_cur[tid] = 0;
    __syncthreads();

    // ---- ROIs: 4 per thread ----
    #pragma unroll
    for (int k = 0; k < 4; k++) {
        int r = tid + k * 1024;
        const float* rp = rois + ((size_t)b * Rn + r) * 9;
        float x = rp[0], y = rp[1];
        float s = 0.f;
        #pragma unroll
        for (int q = 0; q < 9; q++) s += rp[q];
        bool valid = (s != 0.f);
        int lab = labels[b * Rn + r];
        lab = min(max(lab, 0), 9);
        int grp = c_group[lab];
        float sc = scores[b * Rn + r];

        float4 p;
        p.x = x; p.y = y; p.z = sc;
        p.w = __int_as_float(grp + (valid ? 256 : 0));
        g_roi[b * Rn + r] = p;

        // warp-aggregated scatter into (b,grp) bucket
        unsigned vm = __ballot_sync(0xffffffffu, valid);
        if (valid) {
            unsigned peers = __match_any_sync(vm, grp);
            int leader = __ffs(peers) - 1;
            int rank = __popc(peers & ((1u << lane) - 1u));
            int basepos = 0;
            if (lane == leader) basepos = atomicAdd(&sh_cur[grp], __popc(peers));
            basepos = __shfl_sync(peers, basepos, leader);
            float4 e;
            e.x = x; e.y = y; e.z = sc; e.w = __int_as_float(r);
            g_bucket[((size_t)(b * NG + grp)) * Rn + basepos + rank] = e;
        }
    }

    // ---- GTs: threads 0..511 ----
    if (tid < Gn) {
        const float* gp = gt + ((size_t)b * Gn + tid) * 10;
        float s = 0.f;
        #pragma unroll
        for (int q = 0; q < 10; q++) s += gp[q];
        bool valid = (s != 0.f);
        int cls = (int)gp[9];
        cls = min(max(cls, 0), 9);
        int grp = c_group[cls];
        float4 a;
        a.x = gp[0]; a.y = gp[1];
        a.z = adjust_thresh(c_high[cls]);
        a.w = adjust_thresh(c_med[cls]);
        g_gtA[b * Gn + tid] = a;
        g_gtmeta[b * Gn + tid] = valid ? grp : -1;
        float2 xy;
        if (valid) { xy.x = gp[0]; xy.y = gp[1]; }
        else       { xy.x = 1e20f; xy.y = 0.f;  }
        g_gtxy[b * Gn + tid] = xy;
    }

    __syncthreads();
    if (tid < NG) g_bcnt[b * NG + tid] = sh_cur[tid];
}

#define GT_BLOCKS ((Bn * Gn) / 8)      // 8 warps/block, 1 warp = 1 GT -> 512 blocks
#define FP_BLOCKS ((Bn * Rn) / 256)    // 256 threads/block, 1 thread = 1 ROI -> 128

__global__ void __launch_bounds__(256)
ptl_main_kernel(const float* __restrict__ rois,
                const float* __restrict__ gt,
                float* __restrict__ out) {
    if (blockIdx.x < GT_BLOCKS) {
        // ---- per-GT scan over its group bucket: one warp per GT ----
        int warp = (blockIdx.x * blockDim.x + threadIdx.x) >> 5;  // 0..4095
        int lane = threadIdx.x & 31;
        int b = warp >> 9;
        int g = warp & (Gn - 1);

        int meta = g_gtmeta[warp];
        float4 ga = g_gtA[warp];
        float gx = ga.x, gy = ga.y, Th = ga.z, Tm = ga.w;

        unsigned long long keyH = 0ull, keyM = 0ull;

        if (meta >= 0) {
            int cnt = g_bcnt[b * NG + meta];
            const float4* bp = g_bucket + ((size_t)(b * NG + meta)) * Rn;
            #pragma unroll 4
            for (int i = lane; i < cnt; i += 32) {
                float4 p = __ldg(&bp[i]);
                float dx = __fadd_rn(p.x, -gx);
                float dy = __fadd_rn(p.y, -gy);
                float d2 = __fadd_rn(__fmul_rn(dx, dx), __fmul_rn(dy, dy));
                if (d2 <= Tm) {   // rare (~0.4% of pairs)
                    unsigned long long key =
                        ((unsigned long long)(__float_as_uint(p.z) + 1u) << 32) |
                        (unsigned)(~__float_as_int(p.w));
                    if (d2 <= Th) { if (key > keyH) keyH = key; }
                    else          { if (key > keyM) keyM = key; }
                }
            }
        }

        // warp reduce: u64 max (score desc, index asc on ties == jnp.argmax)
        #pragma unroll
        for (int off = 16; off; off >>= 1) {
            unsigned long long kH = __shfl_down_sync(0xffffffffu, keyH, off);
            unsigned long long kM = __shfl_down_sync(0xffffffffu, keyM, off);
            if (kH > keyH) keyH = kH;
            if (kM > keyM) keyM = kM;
        }

        if (lane == 0) {
            float* o = out + (size_t)b * OUTW + g * 35;
            bool hv = (keyH != 0ull);
            bool has_med = (keyM != 0ull);
            bool mv = (!hv) && has_med;
            bool matched = hv || mv;

            if (hv) {
                int idxH = (int)(~(unsigned)keyH);
                float scH = __uint_as_float((unsigned)(keyH >> 32) - 1u);
                const float* hr = rois + ((size_t)b * Rn + idxH) * 9;
                #pragma unroll
                for (int k = 0; k < 9; k++) o[k] = hr[k];
                o[9]  = fminf(__fmul_rn(__fadd_rn(1.2f, scH), 0.5f), 1.0f);
                o[10] = 1.0f;
            } else {
                #pragma unroll
                for (int k = 0; k < 11; k++) o[k] = 0.0f;
            }
            if (mv) {
                int idxM = (int)(~(unsigned)keyM);
                float scM = __uint_as_float((unsigned)(keyM >> 32) - 1u);
                const float* mr = rois + ((size_t)b * Rn + idxM) * 9;
                #pragma unroll
                for (int k = 0; k < 9; k++) o[11 + k] = mr[k];
                o[20] = scM;
                o[21] = 1.0f;
            } else {
                #pragma unroll
                for (int k = 11; k < 22; k++) o[k] = 0.0f;
            }
            const float* gtr = gt + ((size_t)b * Gn + g) * 10;
            if (matched) {
                #pragma unroll
                for (int k = 0; k < 10; k++) o[22 + k] = gtr[k];
            } else {
                #pragma unroll
                for (int k = 0; k < 10; k++) o[22 + k] = 0.0f;
            }
            bool unmatched = (meta >= 0) && !hv && !has_med;
            float nearf = 0.f, midf = 0.f, farf = 0.f;
            if (unmatched) {
                float rng = __fsqrt_rn(__fadd_rn(__fmul_rn(gx, gx), __fmul_rn(gy, gy)));
                if (rng < 30.0f)      nearf = 1.f;
                else if (rng > 50.0f) farf  = 1.f;
                else                  midf  = 1.f;
            }
            o[32] = nearf; o[33] = midf; o[34] = farf;
        }
    } else {
        // ---- per-ROI false-positive pass: one thread per ROI ----
        int bb = blockIdx.x - GT_BLOCKS;          // 0..127
        int b  = bb >> 4;
        int r  = ((bb & 15) << 8) + threadIdx.x;

        __shared__ float4 sgt[Gn / 2];
        for (int j = threadIdx.x; j < Gn / 2; j += 256) {
            float2 a = g_gtxy[b * Gn + 2 * j];
            float2 c = g_gtxy[b * Gn + 2 * j + 1];
            sgt[j] = make_float4(a.x, a.y, c.x, c.y);
        }
        __syncthreads();

        float4 p = g_roi[b * Rn + r];
        float x = p.x, y = p.y;
        float mind2 = __int_as_float(0x7f800000); // +inf
        #pragma unroll 8
        for (int j = 0; j < Gn / 2; j++) {
            float4 q = sgt[j];
            float dx0 = __fadd_rn(x, -q.x);
            float dy0 = __fadd_rn(y, -q.y);
            float d20 = __fadd_rn(__fmul_rn(dx0, dx0), __fmul_rn(dy0, dy0));
            mind2 = fminf(mind2, d20);
            float dx1 = __fadd_rn(x, -q.z);
            float dy1 = __fadd_rn(y, -q.w);
            float d21 = __fadd_rn(__fmul_rn(dx1, dx1), __fmul_rn(dy1, dy1));
            mind2 = fminf(mind2, d21);
        }
        bool valid = (__float_as_int(p.w) & 256) != 0;
        bool fp = valid && (__fsqrt_rn(mind2) > 4.0f);
        float2 o2;
        o2.x = fp ? p.z : 0.f;
        o2.y = fp ? 1.f : 0.f;
        *(float2*)(out + (size_t)b * OUTW + OUTG + (size_t)r * 2) = o2;
    }
}

extern "C" void kernel_launch(void* const* d_in, const int* in_sizes, int n_in,
                              void* d_out, int out_size) {
    const float* rois   = (const float*)d_in[0];
    const float* scores = (const float*)d_in[1];
    const float* gt     = (const float*)d_in[2];
    const int*   labels = (const int*)d_in[3];
    float* out = (float*)d_out;

    ptl_pack_kernel<<<Bn, 1024>>>(rois, scores, labels, gt);
    ptl_main_kernel<<<GT_BLOCKS + FP_BLOCKS, 256>>>(rois, gt, out);
}